// round 1
// baseline (speedup 1.0000x reference)
#include <cuda_runtime.h>
#include <math_constants.h>

#define N_ROWS 131072
#define FEAT   256
#define N_ANC  64
#define ANC    128
#define EPS    1e-5f

#define GRID1  296
#define BLOCK1 512
#define WARPS1 (BLOCK1/32)

// scratch (no allocs allowed)
__device__ float d_v[FEAT];                    // W_send @ a_send[128:]
__device__ float d_partials[GRID1 * 258];      // per-block: acc[256], m, Z
__device__ float d_sr[FEAT];                   // sin(recv)

// ---------------- phase 0: v = W_send @ a2 ----------------
__global__ void k_phase0(const float* __restrict__ W_send,
                         const float* __restrict__ a_send) {
    int k = threadIdx.x;   // 256 threads
    float s = 0.f;
    #pragma unroll 8
    for (int j = 0; j < ANC; j++)
        s += W_send[k * ANC + j] * a_send[ANC + j];
    d_v[k] = s;
}

// ---------------- phase 1: streaming layernorm + logit + online softmax accum ----------------
__global__ void __launch_bounds__(BLOCK1, 2)
k_phase1(const float* __restrict__ feat,
         const float* __restrict__ g_feat,
         const float* __restrict__ b_feat) {
    const int warp = threadIdx.x >> 5;
    const int lane = threadIdx.x & 31;
    const int gwarp = blockIdx.x * WARPS1 + warp;
    const int nwarps = GRID1 * WARPS1;

    // per-lane column slice: columns [lane*8, lane*8+8)
    const float4 v0 = *(const float4*)&d_v[lane * 8];
    const float4 v1 = *(const float4*)&d_v[lane * 8 + 4];
    const float4 g0 = *(const float4*)&g_feat[lane * 8];
    const float4 g1 = *(const float4*)&g_feat[lane * 8 + 4];
    const float4 b0 = *(const float4*)&b_feat[lane * 8];
    const float4 b1 = *(const float4*)&b_feat[lane * 8 + 4];

    float m = -CUDART_INF_F, Z = 0.f;
    float acc[8];
    #pragma unroll
    for (int j = 0; j < 8; j++) acc[j] = 0.f;

    int row = gwarp;
    float4 x0, x1;
    if (row < N_ROWS) {
        const float4* rp = (const float4*)(feat + (size_t)row * FEAT);
        x0 = rp[lane * 2];
        x1 = rp[lane * 2 + 1];
    }
    while (row < N_ROWS) {
        const int nrow = row + nwarps;
        float4 y0, y1;
        if (nrow < N_ROWS) {                 // prefetch next row (MLP)
            const float4* rp = (const float4*)(feat + (size_t)nrow * FEAT);
            y0 = rp[lane * 2];
            y1 = rp[lane * 2 + 1];
        }

        // stats
        float s  = x0.x + x0.y + x0.z + x0.w + x1.x + x1.y + x1.z + x1.w;
        float sq = x0.x*x0.x + x0.y*x0.y + x0.z*x0.z + x0.w*x0.w
                 + x1.x*x1.x + x1.y*x1.y + x1.z*x1.z + x1.w*x1.w;
        #pragma unroll
        for (int off = 16; off; off >>= 1) {
            s  += __shfl_xor_sync(0xffffffffu, s,  off);
            sq += __shfl_xor_sync(0xffffffffu, sq, off);
        }
        const float mu   = s  * (1.f / FEAT);
        const float var  = sq * (1.f / FEAT) - mu * mu;
        const float rstd = rsqrtf(var + EPS);

        float nf[8];
        nf[0] = (x0.x - mu) * rstd * g0.x + b0.x;
        nf[1] = (x0.y - mu) * rstd * g0.y + b0.y;
        nf[2] = (x0.z - mu) * rstd * g0.z + b0.z;
        nf[3] = (x0.w - mu) * rstd * g0.w + b0.w;
        nf[4] = (x1.x - mu) * rstd * g1.x + b1.x;
        nf[5] = (x1.y - mu) * rstd * g1.y + b1.y;
        nf[6] = (x1.z - mu) * rstd * g1.z + b1.z;
        nf[7] = (x1.w - mu) * rstd * g1.w + b1.w;

        float d = nf[0]*v0.x + nf[1]*v0.y + nf[2]*v0.z + nf[3]*v0.w
                + nf[4]*v1.x + nf[5]*v1.y + nf[6]*v1.z + nf[7]*v1.w;
        #pragma unroll
        for (int off = 16; off; off >>= 1)
            d += __shfl_xor_sync(0xffffffffu, d, off);
        const float s2 = d;   // logit, identical on all lanes

        // online softmax
        if (s2 > m) {
            const float sc = __expf(m - s2);
            Z *= sc;
            #pragma unroll
            for (int j = 0; j < 8; j++) acc[j] *= sc;
            m = s2;
        }
        const float w = __expf(s2 - m);
        Z += w;
        #pragma unroll
        for (int j = 0; j < 8; j++) acc[j] += w * nf[j];

        x0 = y0; x1 = y1; row = nrow;
    }

    // ---- block combine ----
    __shared__ float sm[WARPS1], sz[WARPS1];
    __shared__ float sacc[FEAT];
    __shared__ float sM, sZ;

    for (int t = threadIdx.x; t < FEAT; t += BLOCK1) sacc[t] = 0.f;
    if (lane == 0) { sm[warp] = m; sz[warp] = Z; }
    __syncthreads();

    if (threadIdx.x == 0) {
        float M = -CUDART_INF_F;
        for (int w = 0; w < WARPS1; w++) M = fmaxf(M, sm[w]);
        float Zt = 0.f;
        for (int w = 0; w < WARPS1; w++) Zt += sz[w] * __expf(sm[w] - M);
        sM = M; sZ = Zt;
    }
    __syncthreads();

    const float sc = __expf(m - sM);
    #pragma unroll
    for (int j = 0; j < 8; j++)
        atomicAdd(&sacc[lane * 8 + j], acc[j] * sc);
    __syncthreads();

    float* pb = d_partials + blockIdx.x * 258;
    for (int t = threadIdx.x; t < FEAT; t += BLOCK1) pb[t] = sacc[t];
    if (threadIdx.x == 0) { pb[256] = sM; pb[257] = sZ; }
}

// ---------------- phase 2: global merge + tiny matvec chain (1 block, 256 thr) ----------------
__global__ void k_phase2(const float* __restrict__ W_send,
                         const float* __restrict__ anchors,
                         const float* __restrict__ W_recv,
                         const float* __restrict__ g_anc,
                         const float* __restrict__ b_anc) {
    __shared__ float pooled_nf[FEAT];
    __shared__ float pooled[ANC];
    __shared__ float proj[N_ANC];
    __shared__ float na[N_ANC];
    __shared__ float sM, sZ, smu, srstd;

    const int t = threadIdx.x;

    if (t == 0) {
        float M = -CUDART_INF_F;
        for (int b = 0; b < GRID1; b++) M = fmaxf(M, d_partials[b * 258 + 256]);
        float Z = 0.f;
        for (int b = 0; b < GRID1; b++)
            Z += d_partials[b * 258 + 257] * __expf(d_partials[b * 258 + 256] - M);
        sM = M; sZ = Z;
    }
    __syncthreads();

    float a = 0.f;
    for (int b = 0; b < GRID1; b++)
        a += d_partials[b * 258 + t] * __expf(d_partials[b * 258 + 256] - sM);
    pooled_nf[t] = a / sZ;
    __syncthreads();

    // pooled[128] = pooled_nf @ W_send   (W_send row-major [256,128])
    if (t < ANC) {
        float s = 0.f;
        #pragma unroll 8
        for (int k = 0; k < FEAT; k++) s += pooled_nf[k] * W_send[k * ANC + t];
        pooled[t] = s;
    }
    __syncthreads();

    // proj[64] = pooled @ anchors.T   (anchors [64,128])
    if (t < N_ANC) {
        float s = 0.f;
        #pragma unroll 8
        for (int c = 0; c < ANC; c++) s += pooled[c] * anchors[t * ANC + c];
        proj[t] = s;
    }
    __syncthreads();

    if (t == 0) {
        float s = 0.f, sq = 0.f;
        for (int i = 0; i < N_ANC; i++) { s += proj[i]; sq += proj[i] * proj[i]; }
        const float mu  = s  * (1.f / N_ANC);
        const float var = sq * (1.f / N_ANC) - mu * mu;
        smu = mu; srstd = rsqrtf(var + EPS);
    }
    __syncthreads();

    if (t < N_ANC) na[t] = (proj[t] - smu) * srstd * g_anc[t] + b_anc[t];
    __syncthreads();

    // recv[f] = sum_a na[a] * W_recv[a,f]   (W_recv [64,256]);  sr = sin(recv)
    float r = 0.f;
    #pragma unroll 8
    for (int a2 = 0; a2 < N_ANC; a2++) r += na[a2] * W_recv[a2 * FEAT + t];
    d_sr[t] = sinf(r);
}

// ---------------- phase 3: out = features + sr (broadcast) ----------------
__global__ void k_phase3(const float* __restrict__ feat, float* __restrict__ out) {
    __shared__ float4 ssr[FEAT / 4];
    if (threadIdx.x < FEAT / 4) ssr[threadIdx.x] = ((const float4*)d_sr)[threadIdx.x];
    __syncthreads();

    const size_t n4 = (size_t)N_ROWS * FEAT / 4;
    const size_t stride = (size_t)gridDim.x * blockDim.x;
    for (size_t i = (size_t)blockIdx.x * blockDim.x + threadIdx.x; i < n4; i += stride) {
        float4 x = ((const float4*)feat)[i];
        float4 s = ssr[i & (FEAT / 4 - 1)];
        x.x += s.x; x.y += s.y; x.z += s.z; x.w += s.w;
        ((float4*)out)[i] = x;
    }
}

extern "C" void kernel_launch(void* const* d_in, const int* in_sizes, int n_in,
                              void* d_out, int out_size) {
    const float* features = (const float*)d_in[0];
    const float* W_send   = (const float*)d_in[1];
    const float* a_send   = (const float*)d_in[2];
    const float* W_recv   = (const float*)d_in[3];
    // d_in[4] = a_recv (mathematically unused: second softmax is uniform)
    const float* anchors  = (const float*)d_in[5];
    const float* g_feat   = (const float*)d_in[6];
    const float* b_feat   = (const float*)d_in[7];
    const float* g_anc    = (const float*)d_in[8];
    const float* b_anc    = (const float*)d_in[9];
    float* out = (float*)d_out;

    k_phase0<<<1, 256>>>(W_send, a_send);
    k_phase1<<<GRID1, BLOCK1>>>(features, g_feat, b_feat);
    k_phase2<<<1, 256>>>(W_send, anchors, W_recv, g_anc, b_anc);
    k_phase3<<<1184, 512>>>(features, out);
}

// round 2
// speedup vs baseline: 1.0767x; 1.0767x over previous
#include <cuda_runtime.h>
#include <math_constants.h>

#define N_ROWS 131072
#define FEAT   256
#define N_ANC  64
#define ANC    128
#define EPS    1e-5f

#define GRID1  296
#define BLOCK1 512
#define WARPS1 (BLOCK1/32)

// scratch (no allocs allowed)
__device__ float d_v[FEAT];                    // W_send @ a_send[128:]
__device__ float d_partials[GRID1 * 258];      // per-block: acc[256], m, Z
__device__ float d_sr[FEAT];                   // sin(recv)

// ---------------- phase 0: v = W_send @ a2 ----------------
__global__ void k_phase0(const float* __restrict__ W_send,
                         const float* __restrict__ a_send) {
    int k = threadIdx.x;   // 256 threads
    float s = 0.f;
    #pragma unroll 8
    for (int j = 0; j < ANC; j++)
        s += W_send[k * ANC + j] * a_send[ANC + j];
    d_v[k] = s;
}

// ---------------- phase 1: streaming layernorm + logit + online softmax accum ----------------
__global__ void __launch_bounds__(BLOCK1, 2)
k_phase1(const float* __restrict__ feat,
         const float* __restrict__ g_feat,
         const float* __restrict__ b_feat) {
    const int warp = threadIdx.x >> 5;
    const int lane = threadIdx.x & 31;
    const int gwarp = blockIdx.x * WARPS1 + warp;
    const int nwarps = GRID1 * WARPS1;

    // per-lane column slice: columns [lane*8, lane*8+8)
    const float4 v0 = *(const float4*)&d_v[lane * 8];
    const float4 v1 = *(const float4*)&d_v[lane * 8 + 4];
    const float4 g0 = *(const float4*)&g_feat[lane * 8];
    const float4 g1 = *(const float4*)&g_feat[lane * 8 + 4];
    const float4 b0 = *(const float4*)&b_feat[lane * 8];
    const float4 b1 = *(const float4*)&b_feat[lane * 8 + 4];

    float m = -CUDART_INF_F, Z = 0.f;
    float acc[8];
    #pragma unroll
    for (int j = 0; j < 8; j++) acc[j] = 0.f;

    int row = gwarp;
    float4 x0, x1;
    if (row < N_ROWS) {
        const float4* rp = (const float4*)(feat + (size_t)row * FEAT);
        x0 = rp[lane * 2];
        x1 = rp[lane * 2 + 1];
    }
    while (row < N_ROWS) {
        const int nrow = row + nwarps;
        float4 y0, y1;
        if (nrow < N_ROWS) {                 // prefetch next row (MLP)
            const float4* rp = (const float4*)(feat + (size_t)nrow * FEAT);
            y0 = rp[lane * 2];
            y1 = rp[lane * 2 + 1];
        }

        // stats
        float s  = x0.x + x0.y + x0.z + x0.w + x1.x + x1.y + x1.z + x1.w;
        float sq = x0.x*x0.x + x0.y*x0.y + x0.z*x0.z + x0.w*x0.w
                 + x1.x*x1.x + x1.y*x1.y + x1.z*x1.z + x1.w*x1.w;
        #pragma unroll
        for (int off = 16; off; off >>= 1) {
            s  += __shfl_xor_sync(0xffffffffu, s,  off);
            sq += __shfl_xor_sync(0xffffffffu, sq, off);
        }
        const float mu   = s  * (1.f / FEAT);
        const float var  = sq * (1.f / FEAT) - mu * mu;
        const float rstd = rsqrtf(var + EPS);

        float nf[8];
        nf[0] = (x0.x - mu) * rstd * g0.x + b0.x;
        nf[1] = (x0.y - mu) * rstd * g0.y + b0.y;
        nf[2] = (x0.z - mu) * rstd * g0.z + b0.z;
        nf[3] = (x0.w - mu) * rstd * g0.w + b0.w;
        nf[4] = (x1.x - mu) * rstd * g1.x + b1.x;
        nf[5] = (x1.y - mu) * rstd * g1.y + b1.y;
        nf[6] = (x1.z - mu) * rstd * g1.z + b1.z;
        nf[7] = (x1.w - mu) * rstd * g1.w + b1.w;

        float d = nf[0]*v0.x + nf[1]*v0.y + nf[2]*v0.z + nf[3]*v0.w
                + nf[4]*v1.x + nf[5]*v1.y + nf[6]*v1.z + nf[7]*v1.w;
        #pragma unroll
        for (int off = 16; off; off >>= 1)
            d += __shfl_xor_sync(0xffffffffu, d, off);
        const float s2 = d;   // logit, identical on all lanes

        // online softmax
        if (s2 > m) {
            const float sc = __expf(m - s2);
            Z *= sc;
            #pragma unroll
            for (int j = 0; j < 8; j++) acc[j] *= sc;
            m = s2;
        }
        const float w = __expf(s2 - m);
        Z += w;
        #pragma unroll
        for (int j = 0; j < 8; j++) acc[j] += w * nf[j];

        x0 = y0; x1 = y1; row = nrow;
    }

    // ---- block combine ----
    __shared__ float sm[WARPS1], sz[WARPS1];
    __shared__ float sacc[FEAT];
    __shared__ float sM, sZ;

    for (int t = threadIdx.x; t < FEAT; t += BLOCK1) sacc[t] = 0.f;
    if (lane == 0) { sm[warp] = m; sz[warp] = Z; }
    __syncthreads();

    if (threadIdx.x == 0) {
        float M = -CUDART_INF_F;
        for (int w = 0; w < WARPS1; w++) M = fmaxf(M, sm[w]);
        float Zt = 0.f;
        for (int w = 0; w < WARPS1; w++) Zt += sz[w] * __expf(sm[w] - M);
        sM = M; sZ = Zt;
    }
    __syncthreads();

    const float sc = __expf(m - sM);
    #pragma unroll
    for (int j = 0; j < 8; j++)
        atomicAdd(&sacc[lane * 8 + j], acc[j] * sc);
    __syncthreads();

    float* pb = d_partials + blockIdx.x * 258;
    for (int t = threadIdx.x; t < FEAT; t += BLOCK1) pb[t] = sacc[t];
    if (threadIdx.x == 0) { pb[256] = sM; pb[257] = sZ; }
}

// ---------------- phase 2: PARALLEL global merge + tiny matvec chain (1 block, 256 thr) ----------------
__global__ void k_phase2(const float* __restrict__ W_send,
                         const float* __restrict__ anchors,
                         const float* __restrict__ W_recv,
                         const float* __restrict__ g_anc,
                         const float* __restrict__ b_anc) {
    __shared__ float sscale[GRID1];     // exp(m_b - M) per source block
    __shared__ float red[8];
    __shared__ float pooled_nf[FEAT];
    __shared__ float pooled[ANC];
    __shared__ float proj[N_ANC];
    __shared__ float na[N_ANC];
    __shared__ float sM, sZ, smu, srstd;

    const int t = threadIdx.x;          // 256 threads, 8 warps
    const int lane = t & 31;
    const int warp = t >> 5;

    // ---- parallel max over block maxima ----
    float lm = -CUDART_INF_F;
    for (int b = t; b < GRID1; b += 256)
        lm = fmaxf(lm, d_partials[b * 258 + 256]);
    #pragma unroll
    for (int off = 16; off; off >>= 1)
        lm = fmaxf(lm, __shfl_xor_sync(0xffffffffu, lm, off));
    if (lane == 0) red[warp] = lm;
    __syncthreads();
    if (t == 0) {
        float M = red[0];
        #pragma unroll
        for (int w = 1; w < 8; w++) M = fmaxf(M, red[w]);
        sM = M;
    }
    __syncthreads();

    // ---- parallel Z + per-block scale table ----
    float lz = 0.f;
    for (int b = t; b < GRID1; b += 256) {
        const float mb = d_partials[b * 258 + 256];
        const float zb = d_partials[b * 258 + 257];
        const float sc = __expf(mb - sM);
        sscale[b] = sc;
        lz += zb * sc;
    }
    #pragma unroll
    for (int off = 16; off; off >>= 1)
        lz += __shfl_xor_sync(0xffffffffu, lz, off);
    if (lane == 0) red[warp] = lz;
    __syncthreads();
    if (t == 0) {
        float Zt = 0.f;
        #pragma unroll
        for (int w = 0; w < 8; w++) Zt += red[w];
        sZ = Zt;
    }
    __syncthreads();

    // ---- pooled_nf[t] = (1/Z) * sum_b partial_b[t] * scale[b]  (independent loads, MLP-pipelined)
    float a = 0.f;
    #pragma unroll 8
    for (int b = 0; b < GRID1; b++)
        a += d_partials[b * 258 + t] * sscale[b];
    pooled_nf[t] = a / sZ;
    __syncthreads();

    // pooled[128] = pooled_nf @ W_send   (W_send row-major [256,128])
    if (t < ANC) {
        float s = 0.f;
        #pragma unroll 8
        for (int k = 0; k < FEAT; k++) s += pooled_nf[k] * W_send[k * ANC + t];
        pooled[t] = s;
    }
    __syncthreads();

    // proj[64] = pooled @ anchors.T   (anchors [64,128])
    if (t < N_ANC) {
        float s = 0.f;
        #pragma unroll 8
        for (int c = 0; c < ANC; c++) s += pooled[c] * anchors[t * ANC + c];
        proj[t] = s;
    }
    __syncthreads();

    // layernorm over 64 anchors — warp 0 does it with shuffles
    if (warp == 0) {
        float x0 = proj[lane], x1 = proj[lane + 32];
        float s = x0 + x1, sq = x0 * x0 + x1 * x1;
        #pragma unroll
        for (int off = 16; off; off >>= 1) {
            s  += __shfl_xor_sync(0xffffffffu, s,  off);
            sq += __shfl_xor_sync(0xffffffffu, sq, off);
        }
        const float mu  = s  * (1.f / N_ANC);
        const float var = sq * (1.f / N_ANC) - mu * mu;
        if (lane == 0) { smu = mu; srstd = rsqrtf(var + EPS); }
    }
    __syncthreads();

    if (t < N_ANC) na[t] = (proj[t] - smu) * srstd * g_anc[t] + b_anc[t];
    __syncthreads();

    // recv[f] = sum_a na[a] * W_recv[a,f]   (W_recv [64,256]);  sr = sin(recv)
    float r = 0.f;
    #pragma unroll 8
    for (int a2 = 0; a2 < N_ANC; a2++) r += na[a2] * W_recv[a2 * FEAT + t];
    d_sr[t] = sinf(r);
}

// ---------------- phase 3: out = features + sr (broadcast) ----------------
__global__ void k_phase3(const float* __restrict__ feat, float* __restrict__ out) {
    __shared__ float4 ssr[FEAT / 4];
    if (threadIdx.x < FEAT / 4) ssr[threadIdx.x] = ((const float4*)d_sr)[threadIdx.x];
    __syncthreads();

    const size_t n4 = (size_t)N_ROWS * FEAT / 4;
    const size_t stride = (size_t)gridDim.x * blockDim.x;
    for (size_t i = (size_t)blockIdx.x * blockDim.x + threadIdx.x; i < n4; i += stride) {
        float4 x = ((const float4*)feat)[i];
        float4 s = ssr[i & (FEAT / 4 - 1)];
        x.x += s.x; x.y += s.y; x.z += s.z; x.w += s.w;
        ((float4*)out)[i] = x;
    }
}

extern "C" void kernel_launch(void* const* d_in, const int* in_sizes, int n_in,
                              void* d_out, int out_size) {
    const float* features = (const float*)d_in[0];
    const float* W_send   = (const float*)d_in[1];
    const float* a_send   = (const float*)d_in[2];
    const float* W_recv   = (const float*)d_in[3];
    // d_in[4] = a_recv (mathematically unused: second softmax is uniform)
    const float* anchors  = (const float*)d_in[5];
    const float* g_feat   = (const float*)d_in[6];
    const float* b_feat   = (const float*)d_in[7];
    const float* g_anc    = (const float*)d_in[8];
    const float* b_anc    = (const float*)d_in[9];
    float* out = (float*)d_out;

    k_phase0<<<1, 256>>>(W_send, a_send);
    k_phase1<<<GRID1, BLOCK1>>>(features, g_feat, b_feat);
    k_phase2<<<1, 256>>>(W_send, anchors, W_recv, g_anc, b_anc);
    k_phase3<<<1184, 512>>>(features, out);
}